// round 1
// baseline (speedup 1.0000x reference)
#include <cuda_runtime.h>
#include <cstdint>
#include <cstddef>

// Problem dims
#define BB 8192
#define KK 1024   // K per source (two sources: x@Wx, h@Wh)
#define NN 4096   // 4 gates * H
#define HH 1024

// GEMM tiling
#define BM 256
#define BN 128
#define BKT 32
#define THREADS 512
#define PAD 36                      // floats per smem row (32 data + 4 pad) -> conflict-free
#define STAGE_F ((BM + BN) * PAD)   // floats per pipeline stage
#define STAGE_BYTES (STAGE_F * 4)
#define SMEM_BYTES (2 * STAGE_BYTES)
#define KITERS 64                   // 2 sources * (1024/32)

// Scratch for pre-activation gates [B, 4H]
__device__ float g_gates[(size_t)BB * NN];

__device__ __forceinline__ uint32_t f2tf(float f) {
    uint32_t u;
    asm volatile("cvt.rna.tf32.f32 %0, %1;" : "=r"(u) : "f"(f));
    return u;
}

__device__ __forceinline__ void cpa16(uint32_t s, const float* g) {
    asm volatile("cp.async.cg.shared.global [%0], [%1], 16;" :: "r"(s), "l"(g));
}

__device__ __forceinline__ void mma_tf32(float* d, const uint32_t* a, const uint32_t* b) {
    asm volatile(
        "mma.sync.aligned.m16n8k8.row.col.f32.tf32.tf32.f32 "
        "{%0,%1,%2,%3}, {%4,%5,%6,%7}, {%8,%9}, {%0,%1,%2,%3};"
        : "+f"(d[0]), "+f"(d[1]), "+f"(d[2]), "+f"(d[3])
        : "r"(a[0]), "r"(a[1]), "r"(a[2]), "r"(a[3]), "r"(b[0]), "r"(b[1]));
}

// Load one (A 256x32, B 128x32) fp32 tile pair into shared stage via cp.async.
__device__ __forceinline__ void load_tiles(const float* __restrict__ Ag,
                                           const float* __restrict__ Bg,
                                           uint32_t sA, uint32_t sB, int tid) {
#pragma unroll
    for (int i = 0; i < 4; i++) {                  // A: 256 rows * 8 float4 = 2048
        int idx = tid + i * THREADS;
        int row = idx >> 3;
        int seg = (idx & 7) << 2;
        cpa16(sA + (uint32_t)(row * PAD + seg) * 4u, Ag + (size_t)row * KK + seg);
    }
#pragma unroll
    for (int i = 0; i < 2; i++) {                  // B: 128 rows * 8 float4 = 1024
        int idx = tid + i * THREADS;
        int row = idx >> 3;
        int seg = (idx & 7) << 2;
        cpa16(sB + (uint32_t)(row * PAD + seg) * 4u, Bg + (size_t)row * KK + seg);
    }
}

// gates[b, n] = sum_k X[b,k]*Wx[n,k] + sum_k Hs[b,k]*Wh[n,k]
__global__ __launch_bounds__(THREADS) void gates_gemm(
    const float* __restrict__ X, const float* __restrict__ Hs,
    const float* __restrict__ Wx, const float* __restrict__ Wh) {
    extern __shared__ float smem[];
    const int tid  = threadIdx.x;
    const int lane = tid & 31;
    const int wid  = tid >> 5;
    const int wm   = wid & 3;        // 4 warps over M: 64 rows each
    const int wn   = wid >> 2;       // 4 warps over N: 32 cols each
    const int qr   = lane >> 2;
    const int qc   = lane & 3;

    const int m_base = blockIdx.y * BM;
    const int n_base = blockIdx.x * BN;

    uint32_t smem_u = (uint32_t)__cvta_generic_to_shared(smem);

    float acc[4][4][4] = {};

    // ---- prologue: prefetch tile 0 ----
    {
        const float* Asrc = X + (size_t)m_base * KK;
        const float* Bsrc = Wx + (size_t)n_base * KK;
        load_tiles(Asrc, Bsrc, smem_u, smem_u + BM * PAD * 4, tid);
        asm volatile("cp.async.commit_group;");
    }

#pragma unroll 1
    for (int it = 0; it < KITERS; ++it) {
        const int cur = it & 1;
        if (it + 1 < KITERS) {
            const int nit = it + 1;
            const float* Asrc = (nit < 32 ? X : Hs);
            const float* Bsrc = (nit < 32 ? Wx : Wh);
            const int k0 = (nit & 31) * BKT;
            const int ns = cur ^ 1;
            load_tiles(Asrc + (size_t)m_base * KK + k0,
                       Bsrc + (size_t)n_base * KK + k0,
                       smem_u + (uint32_t)ns * STAGE_BYTES,
                       smem_u + (uint32_t)ns * STAGE_BYTES + BM * PAD * 4, tid);
        }
        asm volatile("cp.async.commit_group;");
        asm volatile("cp.async.wait_group 1;");
        __syncthreads();

        const float* sAc = smem + cur * STAGE_F + wm * 64 * PAD;
        const float* sBc = smem + cur * STAGE_F + BM * PAD + wn * 32 * PAD;

#pragma unroll
        for (int ks = 0; ks < BKT; ks += 8) {
            uint32_t a[4][4], b[4][2];
#pragma unroll
            for (int mf = 0; mf < 4; mf++) {
                const float* p = sAc + (mf * 16 + qr) * PAD + ks + qc;
                a[mf][0] = f2tf(p[0]);
                a[mf][1] = f2tf(p[8 * PAD]);
                a[mf][2] = f2tf(p[4]);
                a[mf][3] = f2tf(p[8 * PAD + 4]);
            }
#pragma unroll
            for (int nf = 0; nf < 4; nf++) {
                const float* p = sBc + (nf * 8 + qr) * PAD + ks + qc;
                b[nf][0] = f2tf(p[0]);
                b[nf][1] = f2tf(p[4]);
            }
#pragma unroll
            for (int mf = 0; mf < 4; mf++)
#pragma unroll
                for (int nf = 0; nf < 4; nf++)
                    mma_tf32(acc[mf][nf], a[mf], b[nf]);
        }
        __syncthreads();
    }

    // ---- write accumulators to gates scratch ----
    const int row0 = m_base + wm * 64;
    const int col0 = n_base + wn * 32;
#pragma unroll
    for (int mf = 0; mf < 4; mf++) {
        int row = row0 + mf * 16 + qr;
#pragma unroll
        for (int nf = 0; nf < 4; nf++) {
            int col = col0 + nf * 8 + qc * 2;
            float2 v0 = make_float2(acc[mf][nf][0], acc[mf][nf][1]);
            float2 v1 = make_float2(acc[mf][nf][2], acc[mf][nf][3]);
            *reinterpret_cast<float2*>(&g_gates[(size_t)row * NN + col]) = v0;
            *reinterpret_cast<float2*>(&g_gates[(size_t)(row + 8) * NN + col]) = v1;
        }
    }
}

__device__ __forceinline__ float sigmoidf_(float x) {
    return 1.0f / (1.0f + __expf(-x));
}

__global__ __launch_bounds__(256) void lstm_epilogue(
    const float* __restrict__ c,
    const float* __restrict__ bx, const float* __restrict__ bh,
    float* __restrict__ out) {
    int idx = blockIdx.x * 256 + threadIdx.x;   // 0 .. B*H-1
    int h = idx & (HH - 1);
    const float* grow = g_gates + ((size_t)(idx >> 10) << 12);  // b * 4096

    float gi = grow[h]          + bx[h]          + bh[h];
    float gf = grow[HH + h]     + bx[HH + h]     + bh[HH + h];
    float gg = grow[2 * HH + h] + bx[2 * HH + h] + bh[2 * HH + h];
    float go = grow[3 * HH + h] + bx[3 * HH + h] + bh[3 * HH + h];

    float ig = sigmoidf_(gi);
    float fg = sigmoidf_(gf);
    float g2 = tanhf(gg);
    float og = sigmoidf_(go);

    float nc = fg * c[idx] + ig * g2;
    float nh = og * tanhf(nc);

    out[idx] = nh;
    out[idx + (size_t)BB * HH] = nh;
    out[idx + 2 * (size_t)BB * HH] = nc;
}

extern "C" void kernel_launch(void* const* d_in, const int* in_sizes, int n_in,
                              void* d_out, int out_size) {
    const float* X  = (const float*)d_in[0];  // incoming [B, I]
    const float* Hs = (const float*)d_in[1];  // h        [B, H]
    const float* c  = (const float*)d_in[2];  // c        [B, H]
    const float* Wx = (const float*)d_in[3];  // [4, H, I] -> [4096, 1024]
    const float* Wh = (const float*)d_in[4];  // [4, H, H] -> [4096, 1024]
    const float* bx = (const float*)d_in[5];  // [4, H]
    const float* bh = (const float*)d_in[6];  // [4, H]
    float* out = (float*)d_out;

    cudaFuncSetAttribute(gates_gemm, cudaFuncAttributeMaxDynamicSharedMemorySize,
                         SMEM_BYTES);

    dim3 grid(NN / BN, BB / BM);   // (32, 32); x fastest -> n-blocks share A tile in L2
    gates_gemm<<<grid, THREADS, SMEM_BYTES>>>(X, Hs, Wx, Wh);
    lstm_epilogue<<<(BB * HH) / 256, 256>>>(c, bx, bh, out);
}

// round 3
// speedup vs baseline: 1.3803x; 1.3803x over previous
#include <cuda_runtime.h>
#include <cstdint>
#include <cstddef>

// ---------------- problem dims ----------------
#define BB 8192
#define HH 1024
#define KTOT 2048            // concat K = I + H
#define NNI 4096             // interleaved gate dim n' = 4*h + g

// ---------------- GEMM tiling ----------------
#define BM 256
#define BN 128
#define BK 32
#define THREADS 512
#define KITERS (KTOT / BK)          // 64
#define A_TILE_F4 2048              // 256x32 floats / 4
#define B_TILE_F4 1024              // 128x32 floats / 4
#define A_BYTES (A_TILE_F4 * 16)    // 32768
#define B_BYTES (B_TILE_F4 * 16)    // 16384
#define STAGE_BYTES (A_BYTES + B_BYTES)       // 49152
#define EPI_STRIDE 132              // floats per epilogue smem row (128 + 4 pad)
#define EPI_BYTES (BM * EPI_STRIDE * 4)       // 135168
#define OFF_BIAS EPI_BYTES
#define SMEM_TOTAL (EPI_BYTES + 512)          // 135680  (stages live inside [0, 2*49152))

// ---------------- scratch: fragment-ordered tf32 operands ----------------
// g_A layout: [mb(32)][kt(64)][A-tile 2048 float4], tile = [m16(16)][kstep(4)][lane(32)] x float4
//   float4 for (m16,kstep,lane): qr=lane>>2, qc=lane&3:
//   { A[16m16+qr][8kstep+qc], A[16m16+qr+8][8kstep+qc], A[16m16+qr][8kstep+qc+4], A[16m16+qr+8][8kstep+qc+4] }
__device__ float4 g_A[(size_t)BB * KTOT / 4];
// g_B layout: [nb(32)][kt(64)][B-tile 1024 float4], tile = [pair(8)][kstep(4)][lane(32)] x float4
//   float4: { B[16p+qr][qc], B[16p+qr][qc+4], B[16p+8+qr][qc], B[16p+8+qr][qc+4] }  (qr=lane>>2 in 0..7)
__device__ float4 g_B[(size_t)NNI * KTOT / 4];
__device__ float g_bias[NNI];   // interleaved 4h+g

// ---------------- helpers ----------------
__device__ __forceinline__ float rna_tf32(float x) {
    uint32_t u;
    asm("cvt.rna.tf32.f32 %0, %1;" : "=r"(u) : "f"(x));
    return __uint_as_float(u);
}

__device__ __forceinline__ void cpa16(uint32_t s, const void* g) {
    asm volatile("cp.async.cg.shared.global [%0], [%1], 16;" :: "r"(s), "l"(g));
}

__device__ __forceinline__ void mma_tf32(float* d, const float4& a, float b0, float b1) {
    asm volatile(
        "mma.sync.aligned.m16n8k8.row.col.f32.tf32.tf32.f32 "
        "{%0,%1,%2,%3}, {%4,%5,%6,%7}, {%8,%9}, {%0,%1,%2,%3};"
        : "+f"(d[0]), "+f"(d[1]), "+f"(d[2]), "+f"(d[3])
        : "r"(__float_as_uint(a.x)), "r"(__float_as_uint(a.y)),
          "r"(__float_as_uint(a.z)), "r"(__float_as_uint(a.w)),
          "r"(__float_as_uint(b0)), "r"(__float_as_uint(b1)));
}

__device__ __forceinline__ float sigmoidf_(float x) { return 1.0f / (1.0f + __expf(-x)); }

// ================= pre-pass: round + concat + fragment-order =================
__global__ __launch_bounds__(256) void convert_A(const float* __restrict__ X,
                                                 const float* __restrict__ Hs) {
    size_t idx = (size_t)blockIdx.x * 256 + threadIdx.x;   // float4 index, 2^22 total
    int t     = (int)(idx & 31);
    int v     = (int)((idx >> 5) & 63);
    int kstep = v & 3, m16 = v >> 2;
    int kt    = (int)((idx >> 11) & 63);
    int mb    = (int)(idx >> 17);
    int qr = t >> 2, qc = t & 3;
    int row = mb * 256 + m16 * 16 + qr;
    int k   = kt * 32 + kstep * 8 + qc;

    const float* s0 = (k < 1024) ? X : Hs;
    int kk = k & 1023;
    float4 o;
    o.x = rna_tf32(s0[(size_t)row * 1024 + kk]);
    o.y = rna_tf32(s0[(size_t)(row + 8) * 1024 + kk]);
    const float* s1 = (k + 4 < 1024) ? X : Hs;
    int kk4 = (k + 4) & 1023;
    o.z = rna_tf32(s1[(size_t)row * 1024 + kk4]);
    o.w = rna_tf32(s1[(size_t)(row + 8) * 1024 + kk4]);
    g_A[idx] = o;
}

__global__ __launch_bounds__(256) void convert_B(const float* __restrict__ Wx,
                                                 const float* __restrict__ Wh,
                                                 const float* __restrict__ bx,
                                                 const float* __restrict__ bh) {
    size_t idx = (size_t)blockIdx.x * 256 + threadIdx.x;   // float4 index, 2^21 total
    int t     = (int)(idx & 31);
    int v     = (int)((idx >> 5) & 31);
    int kstep = v & 3, pair = v >> 2;
    int kt    = (int)((idx >> 10) & 63);
    int nb    = (int)(idx >> 16);
    int qr = t >> 2, qc = t & 3;
    int k  = kt * 32 + kstep * 8 + qc;

    int np0 = nb * 128 + pair * 16 + qr;        // n' for first 8-col tile
    int np1 = np0 + 8;                          // second tile of the pair
    // n' = 4h + g  ->  source row in Wx/Wh = g*1024 + h
    int sr0 = (np0 & 3) * 1024 + (np0 >> 2);
    int sr1 = (np1 & 3) * 1024 + (np1 >> 2);

    const float* s0 = (k < 1024) ? Wx : Wh;
    int kk = k & 1023;
    const float* s1 = (k + 4 < 1024) ? Wx : Wh;
    int kk4 = (k + 4) & 1023;
    float4 o;
    o.x = rna_tf32(s0[(size_t)sr0 * 1024 + kk]);
    o.y = rna_tf32(s1[(size_t)sr0 * 1024 + kk4]);
    o.z = rna_tf32(s0[(size_t)sr1 * 1024 + kk]);
    o.w = rna_tf32(s1[(size_t)sr1 * 1024 + kk4]);
    g_B[idx] = o;

    if (kt == 0 && kstep == 0 && qc == 0) {
        g_bias[np0] = bx[sr0] + bh[sr0];
        g_bias[np1] = bx[sr1] + bh[sr1];
    }
}

// ================= fused GEMM + LSTM epilogue =================
__global__ __launch_bounds__(THREADS) void lstm_gemm(const float* __restrict__ cin,
                                                     float* __restrict__ out) {
    extern __shared__ char smem[];
    float* smf = (float*)smem;
    const int tid  = threadIdx.x;
    const int lane = tid & 31;
    const int wid  = tid >> 5;
    const int wm   = wid & 3;       // 4 warps over M (64 rows each)
    const int wn   = wid >> 2;      // 4 warps over N (32 cols each)
    const int qr   = lane >> 2;
    const int qc   = lane & 3;

    const int mb = blockIdx.y;
    const int nb = blockIdx.x;
    const int m_base = mb * BM;
    const int hb = nb * 32;

    uint32_t sb;
    asm("{ .reg .u64 t; cvta.to.shared.u64 t, %1; cvt.u32.u64 %0, t; }" : "=r"(sb) : "l"(smem));

    // bias into smem (lives past the stage region)
    if (tid < 128) smf[OFF_BIAS / 4 + tid] = g_bias[nb * 128 + tid];

    float acc[4][4][4] = {};

    const float4* gA4 = g_A + ((size_t)mb * 64) * A_TILE_F4;
    const float4* gB4 = g_B + ((size_t)nb * 64) * B_TILE_F4;

    // prologue: stage 0
#pragma unroll
    for (int j = 0; j < 4; j++) {
        int ch = j * THREADS + tid;
        cpa16(sb + (uint32_t)ch * 16u, gA4 + ch);
    }
#pragma unroll
    for (int j = 0; j < 2; j++) {
        int ch = j * THREADS + tid;
        cpa16(sb + (uint32_t)(A_BYTES + ch * 16), gB4 + ch);
    }
    asm volatile("cp.async.commit_group;");

#pragma unroll 1
    for (int it = 0; it < KITERS; ++it) {
        const int cur = it & 1;
        if (it + 1 < KITERS) {
            const int ns = cur ^ 1;
            const float4* a_src = gA4 + (size_t)(it + 1) * A_TILE_F4;
            const float4* b_src = gB4 + (size_t)(it + 1) * B_TILE_F4;
            uint32_t base = sb + (uint32_t)ns * STAGE_BYTES;
#pragma unroll
            for (int j = 0; j < 4; j++) {
                int ch = j * THREADS + tid;
                cpa16(base + (uint32_t)ch * 16u, a_src + ch);
            }
#pragma unroll
            for (int j = 0; j < 2; j++) {
                int ch = j * THREADS + tid;
                cpa16(base + (uint32_t)(A_BYTES + ch * 16), b_src + ch);
            }
        }
        asm volatile("cp.async.commit_group;");
        asm volatile("cp.async.wait_group 1;");
        __syncthreads();

        const float4* sA = (const float4*)(smem + cur * STAGE_BYTES) + (wm * 4) * 4 * 32 + lane;
        const float4* sB = (const float4*)(smem + cur * STAGE_BYTES + A_BYTES) + (wn * 2) * 4 * 32 + lane;

#pragma unroll
        for (int ks = 0; ks < 4; ks++) {
            float4 a0 = sA[(0 * 4 + ks) * 32];
            float4 a1 = sA[(1 * 4 + ks) * 32];
            float4 a2 = sA[(2 * 4 + ks) * 32];
            float4 a3 = sA[(3 * 4 + ks) * 32];
            float4 b0 = sB[(0 * 4 + ks) * 32];
            float4 b1 = sB[(1 * 4 + ks) * 32];
#pragma unroll
            for (int mf = 0; mf < 4; mf++) {
                const float4& a = (mf == 0) ? a0 : (mf == 1) ? a1 : (mf == 2) ? a2 : a3;
                mma_tf32(acc[mf][0], a, b0.x, b0.y);
                mma_tf32(acc[mf][1], a, b0.z, b0.w);
                mma_tf32(acc[mf][2], a, b1.x, b1.y);
                mma_tf32(acc[mf][3], a, b1.z, b1.w);
            }
        }
        __syncthreads();
    }

    // ---------------- fused epilogue ----------------
    // 1) accumulators -> smem [256][EPI_STRIDE]
    {
        const int col0 = wn * 32;
#pragma unroll
        for (int mf = 0; mf < 4; mf++) {
            int r = wm * 64 + mf * 16 + qr;
#pragma unroll
            for (int nf = 0; nf < 4; nf++) {
                int cL = col0 + nf * 8 + 2 * qc;
                *(float2*)&smf[r * EPI_STRIDE + cL] = make_float2(acc[mf][nf][0], acc[mf][nf][1]);
                *(float2*)&smf[(r + 8) * EPI_STRIDE + cL] = make_float2(acc[mf][nf][2], acc[mf][nf][3]);
            }
        }
    }
    __syncthreads();

    // 2) read gate-grouped (n' = 4h+g -> float4 = {i,f,g,o}), activate, store
    {
        const int hl = tid & 31;          // h within block (0..31)
        const int rg = tid >> 5;          // 0..15
        float4 bv = *(float4*)&smf[OFF_BIAS / 4 + hl * 4];
        const int h = hb + hl;
#pragma unroll 1
        for (int i = 0; i < 16; i++) {
            int r = i * 16 + rg;
            float4 gt = *(float4*)&smf[r * EPI_STRIDE + hl * 4];
            size_t oidx = (size_t)(m_base + r) * HH + h;
            float cc = cin[oidx];
            float ig = sigmoidf_(gt.x + bv.x);
            float fg = sigmoidf_(gt.y + bv.y);
            float g2 = tanhf(gt.z + bv.z);
            float og = sigmoidf_(gt.w + bv.w);
            float nc = fg * cc + ig * g2;
            float nh = og * tanhf(nc);
            out[oidx] = nh;
            out[oidx + (size_t)BB * HH] = nh;
            out[oidx + 2 * (size_t)BB * HH] = nc;
        }
    }
}

// ================= launch =================
extern "C" void kernel_launch(void* const* d_in, const int* in_sizes, int n_in,
                              void* d_out, int out_size) {
    const float* X  = (const float*)d_in[0];
    const float* Hs = (const float*)d_in[1];
    const float* c  = (const float*)d_in[2];
    const float* Wx = (const float*)d_in[3];
    const float* Wh = (const float*)d_in[4];
    const float* bx = (const float*)d_in[5];
    const float* bh = (const float*)d_in[6];
    float* out = (float*)d_out;

    cudaFuncSetAttribute(lstm_gemm, cudaFuncAttributeMaxDynamicSharedMemorySize, SMEM_TOTAL);

    convert_A<<<(BB * KTOT / 4) / 256, 256>>>(X, Hs);
    convert_B<<<(NNI * KTOT / 4) / 256, 256>>>(Wx, Wh, bx, bh);
    lstm_gemm<<<dim3(NNI / BN, BB / BM), THREADS, SMEM_TOTAL>>>(c, out);
}

// round 4
// speedup vs baseline: 1.4448x; 1.0467x over previous
#include <cuda_runtime.h>
#include <cstdint>
#include <cstddef>

// ---------------- problem dims ----------------
#define BB 8192
#define HH 1024
#define KTOT 2048            // concat K = I + H
#define NNI 4096             // interleaved gate dim n' = 4*h + g

// ---------------- GEMM tiling ----------------
#define BM 256
#define BN 128
#define BK 32
#define THREADS 512
#define NSTAGES 4
#define KITERS (KTOT / BK)          // 64
#define A_TILE_F4 2048              // 256x32 floats / 4
#define B_TILE_F4 1024              // 128x32 floats / 4
#define A_BYTES (A_TILE_F4 * 16)    // 32768
#define B_BYTES (B_TILE_F4 * 16)    // 16384
#define STAGE_BYTES (A_BYTES + B_BYTES)       // 49152
#define STAGE_REGION (NSTAGES * STAGE_BYTES)  // 196608
#define EPI_STRIDE 132              // floats per epilogue smem row (128 + 4 pad)
#define EPI_BYTES (BM * EPI_STRIDE * 4)       // 135168 (overlays stage region)
#define OFF_BIAS STAGE_REGION
#define SMEM_TOTAL (STAGE_REGION + 512)       // 197120

// ---------------- scratch: fragment-ordered tf32 operands ----------------
// g_A: [mb(32)][kt(64)][tile 2048xfloat4], tile = [m16(16)][kstep(4)][lane(32)]
// g_B: [nb(32)][kt(64)][tile 1024xfloat4], tile = [pair(8)][kstep(4)][lane(32)]
__device__ float4 g_A[(size_t)BB * KTOT / 4];
__device__ float4 g_B[(size_t)NNI * KTOT / 4];
__device__ float g_bias[NNI];   // interleaved 4h+g

// ---------------- helpers ----------------
__device__ __forceinline__ float rna_tf32(float x) {
    uint32_t u;
    asm("cvt.rna.tf32.f32 %0, %1;" : "=r"(u) : "f"(x));
    return __uint_as_float(u);
}

__device__ __forceinline__ void cpa16(uint32_t s, const void* g) {
    asm volatile("cp.async.cg.shared.global [%0], [%1], 16;" :: "r"(s), "l"(g));
}

__device__ __forceinline__ void mma_tf32(float* d, const float4& a, float b0, float b1) {
    asm volatile(
        "mma.sync.aligned.m16n8k8.row.col.f32.tf32.tf32.f32 "
        "{%0,%1,%2,%3}, {%4,%5,%6,%7}, {%8,%9}, {%0,%1,%2,%3};"
        : "+f"(d[0]), "+f"(d[1]), "+f"(d[2]), "+f"(d[3])
        : "r"(__float_as_uint(a.x)), "r"(__float_as_uint(a.y)),
          "r"(__float_as_uint(a.z)), "r"(__float_as_uint(a.w)),
          "r"(__float_as_uint(b0)), "r"(__float_as_uint(b1)));
}

__device__ __forceinline__ float sigmoidf_(float x) { return 1.0f / (1.0f + __expf(-x)); }

// ================= pre-pass: round + concat + fragment-order =================
__global__ __launch_bounds__(256) void convert_A(const float* __restrict__ X,
                                                 const float* __restrict__ Hs) {
    size_t idx = (size_t)blockIdx.x * 256 + threadIdx.x;
    int t     = (int)(idx & 31);
    int v     = (int)((idx >> 5) & 63);
    int kstep = v & 3, m16 = v >> 2;
    int kt    = (int)((idx >> 11) & 63);
    int mb    = (int)(idx >> 17);
    int qr = t >> 2, qc = t & 3;
    int row = mb * 256 + m16 * 16 + qr;
    int k   = kt * 32 + kstep * 8 + qc;

    const float* s0 = (k < 1024) ? X : Hs;
    int kk = k & 1023;
    float4 o;
    o.x = rna_tf32(s0[(size_t)row * 1024 + kk]);
    o.y = rna_tf32(s0[(size_t)(row + 8) * 1024 + kk]);
    const float* s1 = (k + 4 < 1024) ? X : Hs;
    int kk4 = (k + 4) & 1023;
    o.z = rna_tf32(s1[(size_t)row * 1024 + kk4]);
    o.w = rna_tf32(s1[(size_t)(row + 8) * 1024 + kk4]);
    g_A[idx] = o;
}

__global__ __launch_bounds__(256) void convert_B(const float* __restrict__ Wx,
                                                 const float* __restrict__ Wh,
                                                 const float* __restrict__ bx,
                                                 const float* __restrict__ bh) {
    size_t idx = (size_t)blockIdx.x * 256 + threadIdx.x;
    int t     = (int)(idx & 31);
    int v     = (int)((idx >> 5) & 31);
    int kstep = v & 3, pair = v >> 2;
    int kt    = (int)((idx >> 10) & 63);
    int nb    = (int)(idx >> 16);
    int qr = t >> 2, qc = t & 3;
    int k  = kt * 32 + kstep * 8 + qc;

    int np0 = nb * 128 + pair * 16 + qr;
    int np1 = np0 + 8;
    int sr0 = (np0 & 3) * 1024 + (np0 >> 2);   // n' = 4h+g -> row g*1024+h
    int sr1 = (np1 & 3) * 1024 + (np1 >> 2);

    const float* s0 = (k < 1024) ? Wx : Wh;
    int kk = k & 1023;
    const float* s1 = (k + 4 < 1024) ? Wx : Wh;
    int kk4 = (k + 4) & 1023;
    float4 o;
    o.x = rna_tf32(s0[(size_t)sr0 * 1024 + kk]);
    o.y = rna_tf32(s1[(size_t)sr0 * 1024 + kk4]);
    o.z = rna_tf32(s0[(size_t)sr1 * 1024 + kk]);
    o.w = rna_tf32(s1[(size_t)sr1 * 1024 + kk4]);
    g_B[idx] = o;

    if (kt == 0 && kstep == 0 && qc == 0) {
        g_bias[np0] = bx[sr0] + bh[sr0];
        g_bias[np1] = bx[sr1] + bh[sr1];
    }
}

// ================= fused GEMM + LSTM epilogue =================
__global__ __launch_bounds__(THREADS) void lstm_gemm(const float* __restrict__ cin,
                                                     float* __restrict__ out) {
    extern __shared__ char smem[];
    float* smf = (float*)smem;
    const int tid  = threadIdx.x;
    const int lane = tid & 31;
    const int wid  = tid >> 5;
    const int wm   = wid & 3;       // 4 warps over M (64 rows each)
    const int wn   = wid >> 2;      // 4 warps over N (32 cols each)
    const int qr   = lane >> 2;
    const int qc   = lane & 3;

    const int mb = blockIdx.y;
    const int nb = blockIdx.x;
    const int m_base = mb * BM;
    const int hb = nb * 32;

    uint32_t sb;
    asm("{ .reg .u64 t; cvta.to.shared.u64 t, %1; cvt.u32.u64 %0, t; }" : "=r"(sb) : "l"(smem));

    if (tid < 128) smf[OFF_BIAS / 4 + tid] = g_bias[nb * 128 + tid];

    float acc[4][4][4] = {};

    const float4* gA4 = g_A + ((size_t)mb * KITERS) * A_TILE_F4;
    const float4* gB4 = g_B + ((size_t)nb * KITERS) * B_TILE_F4;

    // ---- prologue: fill stages 0..2 ----
#pragma unroll
    for (int s = 0; s < NSTAGES - 1; s++) {
        uint32_t base = sb + (uint32_t)s * STAGE_BYTES;
        const float4* a_src = gA4 + (size_t)s * A_TILE_F4;
        const float4* b_src = gB4 + (size_t)s * B_TILE_F4;
#pragma unroll
        for (int j = 0; j < 4; j++) {
            int ch = j * THREADS + tid;
            cpa16(base + (uint32_t)ch * 16u, a_src + ch);
        }
#pragma unroll
        for (int j = 0; j < 2; j++) {
            int ch = j * THREADS + tid;
            cpa16(base + (uint32_t)(A_BYTES + ch * 16), b_src + ch);
        }
        asm volatile("cp.async.commit_group;");
    }

#pragma unroll 1
    for (int it = 0; it < KITERS; ++it) {
        asm volatile("cp.async.wait_group %0;" :: "n"(NSTAGES - 2));
        __syncthreads();

        // issue loads for tile it+3 into stage (it+3)&3 (writes buffer (it-1)&3;
        // its readers finished in compute(it-1), before this barrier)
        if (it + NSTAGES - 1 < KITERS) {
            const int ns = (it + NSTAGES - 1) & (NSTAGES - 1);
            uint32_t base = sb + (uint32_t)ns * STAGE_BYTES;
            const float4* a_src = gA4 + (size_t)(it + NSTAGES - 1) * A_TILE_F4;
            const float4* b_src = gB4 + (size_t)(it + NSTAGES - 1) * B_TILE_F4;
#pragma unroll
            for (int j = 0; j < 4; j++) {
                int ch = j * THREADS + tid;
                cpa16(base + (uint32_t)ch * 16u, a_src + ch);
            }
#pragma unroll
            for (int j = 0; j < 2; j++) {
                int ch = j * THREADS + tid;
                cpa16(base + (uint32_t)(A_BYTES + ch * 16), b_src + ch);
            }
        }
        asm volatile("cp.async.commit_group;");   // empty commit in tail keeps count

        const int cur = it & (NSTAGES - 1);
        const float4* sA = (const float4*)(smem + cur * STAGE_BYTES) + (wm * 4) * 4 * 32 + lane;
        const float4* sB = (const float4*)(smem + cur * STAGE_BYTES + A_BYTES) + (wn * 2) * 4 * 32 + lane;

#pragma unroll
        for (int ks = 0; ks < 4; ks++) {
            float4 a0 = sA[(0 * 4 + ks) * 32];
            float4 a1 = sA[(1 * 4 + ks) * 32];
            float4 a2 = sA[(2 * 4 + ks) * 32];
            float4 a3 = sA[(3 * 4 + ks) * 32];
            float4 b0 = sB[(0 * 4 + ks) * 32];
            float4 b1 = sB[(1 * 4 + ks) * 32];
#pragma unroll
            for (int mf = 0; mf < 4; mf++) {
                const float4& a = (mf == 0) ? a0 : (mf == 1) ? a1 : (mf == 2) ? a2 : a3;
                mma_tf32(acc[mf][0], a, b0.x, b0.y);
                mma_tf32(acc[mf][1], a, b0.z, b0.w);
                mma_tf32(acc[mf][2], a, b1.x, b1.y);
                mma_tf32(acc[mf][3], a, b1.z, b1.w);
            }
        }
    }

    // ---------------- fused epilogue ----------------
    __syncthreads();   // all compute done before overlaying stage region
    {
        const int col0 = wn * 32;
#pragma unroll
        for (int mf = 0; mf < 4; mf++) {
            int r = wm * 64 + mf * 16 + qr;
#pragma unroll
            for (int nf = 0; nf < 4; nf++) {
                int cL = col0 + nf * 8 + 2 * qc;
                *(float2*)&smf[r * EPI_STRIDE + cL] = make_float2(acc[mf][nf][0], acc[mf][nf][1]);
                *(float2*)&smf[(r + 8) * EPI_STRIDE + cL] = make_float2(acc[mf][nf][2], acc[mf][nf][3]);
            }
        }
    }
    __syncthreads();

    {
        const int hl = tid & 31;          // h within block
        const int rg = tid >> 5;          // 0..15
        float4 bv = *(float4*)&smf[OFF_BIAS / 4 + hl * 4];
        const int h = hb + hl;
#pragma unroll 1
        for (int i = 0; i < 16; i++) {
            int r = i * 16 + rg;
            float4 gt = *(float4*)&smf[r * EPI_STRIDE + hl * 4];
            size_t oidx = (size_t)(m_base + r) * HH + h;
            float cc = cin[oidx];
            float ig = sigmoidf_(gt.x + bv.x);
            float fg = sigmoidf_(gt.y + bv.y);
            float g2 = tanhf(gt.z + bv.z);
            float og = sigmoidf_(gt.w + bv.w);
            float nc = fg * cc + ig * g2;
            float nh = og * tanhf(nc);
            out[oidx] = nh;
            out[oidx + (size_t)BB * HH] = nh;
            out[oidx + 2 * (size_t)BB * HH] = nc;
        }
    }
}

// ================= launch =================
extern "C" void kernel_launch(void* const* d_in, const int* in_sizes, int n_in,
                              void* d_out, int out_size) {
    const float* X  = (const float*)d_in[0];
    const float* Hs = (const float*)d_in[1];
    const float* c  = (const float*)d_in[2];
    const float* Wx = (const float*)d_in[3];
    const float* Wh = (const float*)d_in[4];
    const float* bx = (const float*)d_in[5];
    const float* bh = (const float*)d_in[6];
    float* out = (float*)d_out;

    cudaFuncSetAttribute(lstm_gemm, cudaFuncAttributeMaxDynamicSharedMemorySize, SMEM_TOTAL);

    convert_A<<<(BB * KTOT / 4) / 256, 256>>>(X, Hs);
    convert_B<<<(NNI * KTOT / 4) / 256, 256>>>(Wx, Wh, bx, bh);
    lstm_gemm<<<dim3(NNI / BN, BB / BM), THREADS, SMEM_TOTAL>>>(c, out);
}

// round 5
// speedup vs baseline: 2.2915x; 1.5861x over previous
#include <cuda_runtime.h>
#include <cuda_fp16.h>
#include <cstdint>
#include <cstddef>

// ---------------- problem dims ----------------
#define BB 8192
#define HH 1024
#define KTOT 2048            // concat K = I + H
#define NNI 4096             // interleaved gate dim n' = 4*h + g

// ---------------- GEMM tiling ----------------
#define BM 256
#define BN 128
#define BK 32
#define THREADS 512
#define NSTAGES 6
#define KITERS (KTOT / BK)           // 64
#define A_TILE_U4 1024               // 256x32 halves / 8
#define B_TILE_U4 512                // 128x32 halves / 8
#define A_BYTES (A_TILE_U4 * 16)     // 16384
#define B_BYTES (B_TILE_U4 * 16)     // 8192
#define STAGE_BYTES (A_BYTES + B_BYTES)        // 24576
#define STAGE_REGION (NSTAGES * STAGE_BYTES)   // 147456
#define EPI_STRIDE 132
#define EPI_BYTES (BM * EPI_STRIDE * 4)        // 135168 (overlays stage region)
#define OFF_BIAS STAGE_REGION
#define SMEM_TOTAL (STAGE_REGION + 512)        // 147968

// ---------------- scratch: fragment-ordered fp16 operands ----------------
// g_A: [mb(32)][kt(64)][m16(16)][ks(2)][lane(32)] x uint4
//      uint4 = {h2(A[R][C],A[R][C+1]), h2(A[R+8][C],A[R+8][C+1]),
//               h2(A[R][C+8],A[R][C+9]), h2(A[R+8][C+8],A[R+8][C+9])}
//      R = mb*256+m16*16+qr, C = kt*32+ks*16+2qc  (qr=lane>>2, qc=lane&3)
__device__ uint4 g_A[(size_t)BB * KTOT / 8];
// g_B: [nb(32)][kt(64)][wn(4)][p(2)][ks(2)][lane(32)] x uint4
//      uint4 = {h2(B[N0][C],B[N0][C+1]), h2(B[N0][C+8],B[N0][C+9]),
//               h2(B[N1][C],B[N1][C+1]), h2(B[N1][C+8],B[N1][C+9])}
//      N0 = nb*128+wn*32+p*16+qr, N1 = N0+8
__device__ uint4 g_B[(size_t)NNI * KTOT / 8];
__device__ float g_bias[NNI];   // interleaved 4h+g

// ---------------- helpers ----------------
__device__ __forceinline__ void cpa16(uint32_t s, const void* g) {
    asm volatile("cp.async.cg.shared.global [%0], [%1], 16;" :: "r"(s), "l"(g));
}

__device__ __forceinline__ uint32_t h2pack(float lo, float hi) {
    __half2 h = __floats2half2_rn(lo, hi);
    return *reinterpret_cast<uint32_t*>(&h);
}

__device__ __forceinline__ void mma_f16(float* d, const uint4& a, uint32_t b0, uint32_t b1) {
    asm volatile(
        "mma.sync.aligned.m16n8k16.row.col.f32.f16.f16.f32 "
        "{%0,%1,%2,%3}, {%4,%5,%6,%7}, {%8,%9}, {%0,%1,%2,%3};"
        : "+f"(d[0]), "+f"(d[1]), "+f"(d[2]), "+f"(d[3])
        : "r"(a.x), "r"(a.y), "r"(a.z), "r"(a.w), "r"(b0), "r"(b1));
}

__device__ __forceinline__ float sigmoidf_(float x) { return 1.0f / (1.0f + __expf(-x)); }

// ================= pre-pass: fp16-round + concat + fragment-order =================
__global__ __launch_bounds__(256) void convert_A(const float* __restrict__ X,
                                                 const float* __restrict__ Hs) {
    size_t idx = (size_t)blockIdx.x * 256 + threadIdx.x;   // uint4 entries, 2^21 total
    int lane = (int)(idx & 31);
    int ks   = (int)((idx >> 5) & 1);
    int m16  = (int)((idx >> 6) & 15);
    int kt   = (int)((idx >> 10) & 63);
    int mb   = (int)(idx >> 16);
    int qr = lane >> 2, qc = lane & 3;
    int R = mb * 256 + m16 * 16 + qr;
    int C = kt * 32 + ks * 16 + 2 * qc;       // C,C+1,C+8,C+9 all in one source

    const float* src = (C < 1024) ? X : Hs;
    int c0 = C & 1023;
    float2 r0a = *(const float2*)&src[(size_t)R * 1024 + c0];
    float2 r0b = *(const float2*)&src[(size_t)R * 1024 + c0 + 8];
    float2 r1a = *(const float2*)&src[(size_t)(R + 8) * 1024 + c0];
    float2 r1b = *(const float2*)&src[(size_t)(R + 8) * 1024 + c0 + 8];

    uint4 o;
    o.x = h2pack(r0a.x, r0a.y);
    o.y = h2pack(r1a.x, r1a.y);
    o.z = h2pack(r0b.x, r0b.y);
    o.w = h2pack(r1b.x, r1b.y);
    g_A[idx] = o;
}

__global__ __launch_bounds__(256) void convert_B(const float* __restrict__ Wx,
                                                 const float* __restrict__ Wh,
                                                 const float* __restrict__ bx,
                                                 const float* __restrict__ bh) {
    size_t idx = (size_t)blockIdx.x * 256 + threadIdx.x;   // uint4 entries, 2^20 total
    int lane = (int)(idx & 31);
    int ks   = (int)((idx >> 5) & 1);
    int p    = (int)((idx >> 6) & 1);
    int wn   = (int)((idx >> 7) & 3);
    int kt   = (int)((idx >> 9) & 63);
    int nb   = (int)(idx >> 15);
    int qr = lane >> 2, qc = lane & 3;
    int C = kt * 32 + ks * 16 + 2 * qc;
    int N0 = nb * 128 + wn * 32 + p * 16 + qr;
    int N1 = N0 + 8;
    int sr0 = (N0 & 3) * 1024 + (N0 >> 2);    // n' = 4h+g -> row g*1024+h
    int sr1 = (N1 & 3) * 1024 + (N1 >> 2);

    const float* src = (C < 1024) ? Wx : Wh;
    int c0 = C & 1023;
    float2 w0a = *(const float2*)&src[(size_t)sr0 * 1024 + c0];
    float2 w0b = *(const float2*)&src[(size_t)sr0 * 1024 + c0 + 8];
    float2 w1a = *(const float2*)&src[(size_t)sr1 * 1024 + c0];
    float2 w1b = *(const float2*)&src[(size_t)sr1 * 1024 + c0 + 8];

    uint4 o;
    o.x = h2pack(w0a.x, w0a.y);
    o.y = h2pack(w0b.x, w0b.y);
    o.z = h2pack(w1a.x, w1a.y);
    o.w = h2pack(w1b.x, w1b.y);
    g_B[idx] = o;

    if (kt == 0 && ks == 0 && qc == 0) {
        g_bias[N0] = bx[sr0] + bh[sr0];
        g_bias[N1] = bx[sr1] + bh[sr1];
    }
}

// ================= fused GEMM + LSTM epilogue =================
__global__ __launch_bounds__(THREADS) void lstm_gemm(const float* __restrict__ cin,
                                                     float* __restrict__ out) {
    extern __shared__ char smem[];
    float* smf = (float*)smem;
    const int tid  = threadIdx.x;
    const int lane = tid & 31;
    const int wid  = tid >> 5;
    const int wm   = wid & 3;       // 4 warps over M (64 rows each)
    const int wn   = wid >> 2;      // 4 warps over N (32 cols each)
    const int qr   = lane >> 2;
    const int qc   = lane & 3;

    const int mb = blockIdx.y;
    const int nb = blockIdx.x;
    const int m_base = mb * BM;
    const int hb = nb * 32;

    uint32_t sb;
    asm("{ .reg .u64 t; cvta.to.shared.u64 t, %1; cvt.u32.u64 %0, t; }" : "=r"(sb) : "l"(smem));

    if (tid < 128) smf[OFF_BIAS / 4 + tid] = g_bias[nb * 128 + tid];

    float acc[4][4][4] = {};

    const uint4* gA4 = g_A + ((size_t)mb * KITERS) * A_TILE_U4;
    const uint4* gB4 = g_B + ((size_t)nb * KITERS) * B_TILE_U4;

    // ---- prologue: fill stages 0..NSTAGES-2 ----
#pragma unroll
    for (int s = 0; s < NSTAGES - 1; s++) {
        uint32_t base = sb + (uint32_t)s * STAGE_BYTES;
        const uint4* a_src = gA4 + (size_t)s * A_TILE_U4;
        const uint4* b_src = gB4 + (size_t)s * B_TILE_U4;
#pragma unroll
        for (int j = 0; j < 2; j++) {
            int ch = j * THREADS + tid;
            cpa16(base + (uint32_t)ch * 16u, a_src + ch);
        }
        cpa16(base + (uint32_t)(A_BYTES + tid * 16), b_src + tid);
        asm volatile("cp.async.commit_group;");
    }

#pragma unroll 1
    for (int it = 0; it < KITERS; ++it) {
        asm volatile("cp.async.wait_group %0;" :: "n"(NSTAGES - 2));
        __syncthreads();

        if (it + NSTAGES - 1 < KITERS) {
            const int ns = (it + NSTAGES - 1) % NSTAGES;
            uint32_t base = sb + (uint32_t)ns * STAGE_BYTES;
            const uint4* a_src = gA4 + (size_t)(it + NSTAGES - 1) * A_TILE_U4;
            const uint4* b_src = gB4 + (size_t)(it + NSTAGES - 1) * B_TILE_U4;
#pragma unroll
            for (int j = 0; j < 2; j++) {
                int ch = j * THREADS + tid;
                cpa16(base + (uint32_t)ch * 16u, a_src + ch);
            }
            cpa16(base + (uint32_t)(A_BYTES + tid * 16), b_src + tid);
        }
        asm volatile("cp.async.commit_group;");   // empty commit in tail keeps count

        const int cur = it % NSTAGES;
        const uint4* sA = (const uint4*)(smem + cur * STAGE_BYTES) + lane;
        const uint4* sB = (const uint4*)(smem + cur * STAGE_BYTES + A_BYTES) + lane;

#pragma unroll
        for (int ks = 0; ks < 2; ks++) {
            uint4 a0 = sA[((wm * 4 + 0) * 2 + ks) * 32];
            uint4 a1 = sA[((wm * 4 + 1) * 2 + ks) * 32];
            uint4 a2 = sA[((wm * 4 + 2) * 2 + ks) * 32];
            uint4 a3 = sA[((wm * 4 + 3) * 2 + ks) * 32];
            uint4 b0 = sB[((wn * 2 + 0) * 2 + ks) * 32];
            uint4 b1 = sB[((wn * 2 + 1) * 2 + ks) * 32];
#pragma unroll
            for (int mf = 0; mf < 4; mf++) {
                const uint4& a = (mf == 0) ? a0 : (mf == 1) ? a1 : (mf == 2) ? a2 : a3;
                mma_f16(acc[mf][0], a, b0.x, b0.y);
                mma_f16(acc[mf][1], a, b0.z, b0.w);
                mma_f16(acc[mf][2], a, b1.x, b1.y);
                mma_f16(acc[mf][3], a, b1.z, b1.w);
            }
        }
    }

    // ---------------- fused epilogue ----------------
    asm volatile("cp.async.wait_group 0;");
    __syncthreads();   // all compute + async writes done before overlaying stage region
    {
        const int col0 = wn * 32;
#pragma unroll
        for (int mf = 0; mf < 4; mf++) {
            int r = wm * 64 + mf * 16 + qr;
#pragma unroll
            for (int nf = 0; nf < 4; nf++) {
                int cL = col0 + nf * 8 + 2 * qc;
                *(float2*)&smf[r * EPI_STRIDE + cL] = make_float2(acc[mf][nf][0], acc[mf][nf][1]);
                *(float2*)&smf[(r + 8) * EPI_STRIDE + cL] = make_float2(acc[mf][nf][2], acc[mf][nf][3]);
            }
        }
    }
    __syncthreads();

    {
        const int hl = tid & 31;          // h within block
        const int rg = tid >> 5;          // 0..15
        float4 bv = *(float4*)&smf[OFF_BIAS / 4 + hl * 4];
        const int h = hb + hl;
#pragma unroll 1
        for (int i = 0; i < 16; i++) {
            int r = i * 16 + rg;
            float4 gt = *(float4*)&smf[r * EPI_STRIDE + hl * 4];
            size_t oidx = (size_t)(m_base + r) * HH + h;
            float cc = cin[oidx];
            float ig = sigmoidf_(gt.x + bv.x);
            float fg = sigmoidf_(gt.y + bv.y);
            float g2 = tanhf(gt.z + bv.z);
            float og = sigmoidf_(gt.w + bv.w);
            float nc = fg * cc + ig * g2;
            float nh = og * tanhf(nc);
            out[oidx] = nh;
            out[oidx + (size_t)BB * HH] = nh;
            out[oidx + 2 * (size_t)BB * HH] = nc;
        }
    }
}

// ================= launch =================
extern "C" void kernel_launch(void* const* d_in, const int* in_sizes, int n_in,
                              void* d_out, int out_size) {
    const float* X  = (const float*)d_in[0];
    const float* Hs = (const float*)d_in[1];
    const float* c  = (const float*)d_in[2];
    const float* Wx = (const float*)d_in[3];
    const float* Wh = (const float*)d_in[4];
    const float* bx = (const float*)d_in[5];
    const float* bh = (const float*)d_in[6];
    float* out = (float*)d_out;

    cudaFuncSetAttribute(lstm_gemm, cudaFuncAttributeMaxDynamicSharedMemorySize, SMEM_TOTAL);

    convert_A<<<(BB * KTOT / 8) / 256, 256>>>(X, Hs);
    convert_B<<<(NNI * KTOT / 8) / 256, 256>>>(Wx, Wh, bx, bh);
    lstm_gemm<<<dim3(NNI / BN, BB / BM), THREADS, SMEM_TOTAL>>>(c, out);
}

// round 9
// speedup vs baseline: 2.4786x; 1.0816x over previous
#include <cuda_runtime.h>
#include <cuda_fp16.h>
#include <cstdint>
#include <cstddef>

// ---------------- problem dims ----------------
#define BB 8192
#define HH 1024
#define KTOT 2048            // concat K = I + H
#define NNI 4096             // interleaved gate dim n' = 4*h + g

// ---------------- GEMM tiling ----------------
#define BM 256
#define BN 128
#define THREADS 512
#define NSTAGES 3
#define KITERS2 32                   // mainloop iterations, 64 K each
#define SUB_A_U4 1024                // one 32-K A subtile in uint4
#define SUB_B_U4 512
#define A_TILE_U4 (2 * SUB_A_U4)     // 64-K stage A part = 2048 uint4 = 32KB
#define B_TILE_U4 (2 * SUB_B_U4)     // 1024 uint4 = 16KB
#define A_BYTES (A_TILE_U4 * 16)     // 32768
#define B_BYTES (B_TILE_U4 * 16)     // 16384
#define STAGE_BYTES (A_BYTES + B_BYTES)        // 49152
#define STAGE_REGION (NSTAGES * STAGE_BYTES)   // 147456
#define EPI_STRIDE 132
#define EPI_BYTES (BM * EPI_STRIDE * 4)        // 135168 (overlays stage region)
#define OFF_BIAS STAGE_REGION
#define SMEM_TOTAL (STAGE_REGION + 512)        // 147968

// ---------------- scratch: fragment-ordered fp16 operands (same layout as R5) ----------------
// g_A: [mb(32)][kt32(64)][m16(16)][ks(2)][lane(32)] x uint4
__device__ uint4 g_A[(size_t)BB * KTOT / 8];
// g_B: [nb(32)][kt32(64)][wn(4)][p(2)][ks(2)][lane(32)] x uint4
__device__ uint4 g_B[(size_t)NNI * KTOT / 8];
__device__ float g_bias[NNI];   // interleaved 4h+g

// ---------------- helpers ----------------
__device__ __forceinline__ void cpa16(uint32_t s, const void* g) {
    asm volatile("cp.async.cg.shared.global [%0], [%1], 16;" :: "r"(s), "l"(g));
}

__device__ __forceinline__ uint32_t h2pack(float lo, float hi) {
    __half2 h = __floats2half2_rn(lo, hi);
    return *reinterpret_cast<uint32_t*>(&h);
}

__device__ __forceinline__ void mma_f16(float* d, const uint4& a, uint32_t b0, uint32_t b1) {
    asm volatile(
        "mma.sync.aligned.m16n8k16.row.col.f32.f16.f16.f32 "
        "{%0,%1,%2,%3}, {%4,%5,%6,%7}, {%8,%9}, {%0,%1,%2,%3};"
        : "+f"(d[0]), "+f"(d[1]), "+f"(d[2]), "+f"(d[3])
        : "r"(a.x), "r"(a.y), "r"(a.z), "r"(a.w), "r"(b0), "r"(b1));
}

__device__ __forceinline__ float fast_sigmoid(float x) {
    return __fdividef(1.0f, 1.0f + __expf(-x));
}
__device__ __forceinline__ float fast_tanh(float x) {
    // 2*sigmoid(2x) - 1 ; robust at +/-inf, err ~1e-6
    return __fmaf_rn(2.0f, __fdividef(1.0f, 1.0f + __expf(-2.0f * x)), -1.0f);
}

// ================= pre-pass: fp16-round + concat + fragment-order =================
__global__ __launch_bounds__(256) void convert_A(const float* __restrict__ X,
                                                 const float* __restrict__ Hs) {
    size_t idx = (size_t)blockIdx.x * 256 + threadIdx.x;   // uint4 entries, 2^21 total
    int lane = (int)(idx & 31);
    int ks   = (int)((idx >> 5) & 1);
    int m16  = (int)((idx >> 6) & 15);
    int kt   = (int)((idx >> 10) & 63);
    int mb   = (int)(idx >> 16);
    int qr = lane >> 2, qc = lane & 3;
    int R = mb * 256 + m16 * 16 + qr;
    int C = kt * 32 + ks * 16 + 2 * qc;

    const float* src = (C < 1024) ? X : Hs;
    int c0 = C & 1023;
    float2 r0a = *(const float2*)&src[(size_t)R * 1024 + c0];
    float2 r0b = *(const float2*)&src[(size_t)R * 1024 + c0 + 8];
    float2 r1a = *(const float2*)&src[(size_t)(R + 8) * 1024 + c0];
    float2 r1b = *(const float2*)&src[(size_t)(R + 8) * 1024 + c0 + 8];

    uint4 o;
    o.x = h2pack(r0a.x, r0a.y);
    o.y = h2pack(r1a.x, r1a.y);
    o.z = h2pack(r0b.x, r0b.y);
    o.w = h2pack(r1b.x, r1b.y);
    g_A[idx] = o;
}

__global__ __launch_bounds__(256) void convert_B(const float* __restrict__ Wx,
                                                 const float* __restrict__ Wh,
                                                 const float* __restrict__ bx,
                                                 const float* __restrict__ bh) {
    size_t idx = (size_t)blockIdx.x * 256 + threadIdx.x;   // uint4 entries, 2^20 total
    int lane = (int)(idx & 31);
    int ks   = (int)((idx >> 5) & 1);
    int p    = (int)((idx >> 6) & 1);
    int wn   = (int)((idx >> 7) & 3);
    int kt   = (int)((idx >> 9) & 63);
    int nb   = (int)(idx >> 15);
    int qr = lane >> 2, qc = lane & 3;
    int C = kt * 32 + ks * 16 + 2 * qc;
    int N0 = nb * 128 + wn * 32 + p * 16 + qr;
    int N1 = N0 + 8;
    int sr0 = (N0 & 3) * 1024 + (N0 >> 2);    // n' = 4h+g -> row g*1024+h
    int sr1 = (N1 & 3) * 1024 + (N1 >> 2);

    const float* src = (C < 1024) ? Wx : Wh;
    int c0 = C & 1023;
    float2 w0a = *(const float2*)&src[(size_t)sr0 * 1024 + c0];
    float2 w0b = *(const float2*)&src[(size_t)sr0 * 1024 + c0 + 8];
    float2 w1a = *(const float2*)&src[(size_t)sr1 * 1024 + c0];
    float2 w1b = *(const float2*)&src[(size_t)sr1 * 1024 + c0 + 8];

    uint4 o;
    o.x = h2pack(w0a.x, w0a.y);
    o.y = h2pack(w0b.x, w0b.y);
    o.z = h2pack(w1a.x, w1a.y);
    o.w = h2pack(w1b.x, w1b.y);
    g_B[idx] = o;

    if (kt == 0 && ks == 0 && qc == 0) {
        g_bias[N0] = bx[sr0] + bh[sr0];
        g_bias[N1] = bx[sr1] + bh[sr1];
    }
}

// ================= fused GEMM + LSTM epilogue =================
__global__ __launch_bounds__(THREADS) void lstm_gemm(const float* __restrict__ cin,
                                                     float* __restrict__ out) {
    extern __shared__ char smem[];
    float* smf = (float*)smem;
    const int tid  = threadIdx.x;
    const int lane = tid & 31;
    const int wid  = tid >> 5;
    const int wm   = wid & 3;       // 4 warps over M (64 rows each)
    const int wn   = wid >> 2;      // 4 warps over N (32 cols each)
    const int qr   = lane >> 2;
    const int qc   = lane & 3;

    const int mb = blockIdx.y;
    const int nb = blockIdx.x;
    const int m_base = mb * BM;
    const int hb = nb * 32;

    uint32_t sb;
    asm("{ .reg .u64 t; cvta.to.shared.u64 t, %1; cvt.u32.u64 %0, t; }" : "=r"(sb) : "l"(smem));

    if (tid < 128) smf[OFF_BIAS / 4 + tid] = g_bias[nb * 128 + tid];

    float acc[4][4][4] = {};

    // one mainloop iteration consumes 2 consecutive 32-K subtiles
    const uint4* gA4 = g_A + ((size_t)mb * 64) * SUB_A_U4;
    const uint4* gB4 = g_B + ((size_t)nb * 64) * SUB_B_U4;

    // ---- prologue: fill stages 0..1 ----
#pragma unroll
    for (int s = 0; s < NSTAGES - 1; s++) {
        uint32_t base = sb + (uint32_t)s * STAGE_BYTES;
        const uint4* a_src = gA4 + (size_t)s * A_TILE_U4;
        const uint4* b_src = gB4 + (size_t)s * B_TILE_U4;
#pragma unroll
        for (int j = 0; j < 4; j++) {
            int ch = j * THREADS + tid;
            cpa16(base + (uint32_t)ch * 16u, a_src + ch);
        }
#pragma unroll
        for (int j = 0; j < 2; j++) {
            int ch = j * THREADS + tid;
            cpa16(base + (uint32_t)(A_BYTES + ch * 16), b_src + ch);
        }
        asm volatile("cp.async.commit_group;");
    }

#pragma unroll 1
    for (int it = 0; it < KITERS2; ++it) {
        asm volatile("cp.async.wait_group %0;" :: "n"(NSTAGES - 2));
        __syncthreads();

        if (it + NSTAGES - 1 < KITERS2) {
            const int ns = (it + NSTAGES - 1) % NSTAGES;
            uint32_t base = sb + (uint32_t)ns * STAGE_BYTES;
            const uint4* a_src = gA4 + (size_t)(it + NSTAGES - 1) * A_TILE_U4;
            const uint4* b_src = gB4 + (size_t)(it + NSTAGES - 1) * B_TILE_U4;
#pragma unroll
            for (int j = 0; j < 4; j++) {
                int ch = j * THREADS + tid;
                cpa16(base + (uint32_t)ch * 16u, a_src + ch);
            }
#pragma unroll
            for (int j = 0; j < 2; j++) {
                int ch = j * THREADS + tid;
                cpa16(base + (uint32_t)(A_BYTES + ch * 16), b_src + ch);
            }
        }
        asm volatile("cp.async.commit_group;");   // empty commit in tail keeps count

        const int cur = it % NSTAGES;
        const uint4* sA = (const uint4*)(smem + cur * STAGE_BYTES) + lane;
        const uint4* sB = (const uint4*)(smem + cur * STAGE_BYTES + A_BYTES) + lane;

#pragma unroll
        for (int ks2 = 0; ks2 < 4; ks2++) {       // 4 x 16-K steps per iteration
            const int aoff = (ks2 >> 1) * SUB_A_U4 + (ks2 & 1) * 32;
            const int boff = (ks2 >> 1) * SUB_B_U4 + (ks2 & 1) * 32;
            uint4 a0 = sA[aoff + (wm * 4 + 0) * 64];
            uint4 a1 = sA[aoff + (wm * 4 + 1) * 64];
            uint4 a2 = sA[aoff + (wm * 4 + 2) * 64];
            uint4 a3 = sA[aoff + (wm * 4 + 3) * 64];
            uint4 b0 = sB[boff + (wn * 2 + 0) * 64];
            uint4 b1 = sB[boff + (wn * 2 + 1) * 64];
#pragma unroll
            for (int mf = 0; mf < 4; mf++) {
                const uint4& a = (mf == 0) ? a0 : (mf == 1) ? a1 : (mf == 2) ? a2 : a3;
                mma_f16(acc[mf][0], a, b0.x, b0.y);
                mma_f16(acc[mf][1], a, b0.z, b0.w);
                mma_f16(acc[mf][2], a, b1.x, b1.y);
                mma_f16(acc[mf][3], a, b1.z, b1.w);
            }
        }
    }

    // ---------------- fused epilogue ----------------
    asm volatile("cp.async.wait_group 0;");
    __syncthreads();   // all compute + async writes done before overlaying stage region
    {
        const int col0 = wn * 32;
#pragma unroll
        for (int mf = 0; mf < 4; mf++) {
            int r = wm * 64 + mf * 16 + qr;
#pragma unroll
            for (int nf = 0; nf < 4; nf++) {
                int cL = col0 + nf * 8 + 2 * qc;
                *(float2*)&smf[r * EPI_STRIDE + cL] = make_float2(acc[mf][nf][0], acc[mf][nf][1]);
                *(float2*)&smf[(r + 8) * EPI_STRIDE + cL] = make_float2(acc[mf][nf][2], acc[mf][nf][3]);
            }
        }
    }
    __syncthreads();

    {
        const int hl = tid & 31;          // h within block
        const int rg = tid >> 5;          // 0..15
        float4 bv = *(float4*)&smf[OFF_BIAS / 4 + hl * 4];
        const int h = hb + hl;
#pragma unroll 1
        for (int i = 0; i < 16; i++) {
            int r = i * 16 + rg;
            float4 gt = *(float4*)&smf[r * EPI_STRIDE + hl * 4];
            size_t oidx = (size_t)(m_base + r) * HH + h;
            float cc = cin[oidx];
            float ig = fast_sigmoid(gt.x + bv.x);
            float fg = fast_sigmoid(gt.y + bv.y);
            float g2 = fast_tanh(gt.z + bv.z);
            float og = fast_sigmoid(gt.w + bv.w);
            float nc = fg * cc + ig * g2;
            float nh = og * fast_tanh(nc);
            out[oidx] = nh;
            out[oidx + (size_t)BB * HH] = nh;
            out[oidx + 2 * (size_t)BB * HH] = nc;
        }
    }
}

// ================= launch =================
extern "C" void kernel_launch(void* const* d_in, const int* in_sizes, int n_in,
                              void* d_out, int out_size) {
    const float* X  = (const float*)d_in[0];
    const float* Hs = (const float*)d_in[1];
    const float* c  = (const float*)d_in[2];
    const float* Wx = (const float*)d_in[3];
    const float* Wh = (const float*)d_in[4];
    const float* bx = (const float*)d_in[5];
    const float* bh = (const float*)d_in[6];
    float* out = (float*)d_out;

    cudaFuncSetAttribute(lstm_gemm, cudaFuncAttributeMaxDynamicSharedMemorySize, SMEM_TOTAL);

    convert_A<<<(BB * KTOT / 8) / 256, 256>>>(X, Hs);
    convert_B<<<(NNI * KTOT / 8) / 256, 256>>>(Wx, Wh, bx, bh);
    lstm_gemm<<<dim3(NNI / BN, BB / BM), THREADS, SMEM_TOTAL>>>(c, out);
}

// round 10
// speedup vs baseline: 2.7652x; 1.1156x over previous
#include <cuda_runtime.h>
#include <cuda_fp16.h>
#include <cstdint>
#include <cstddef>

// ---------------- problem dims ----------------
#define BB 8192
#define HH 1024
#define KTOT 2048            // concat K = I + H
#define NNI 4096             // interleaved gate dim n' = 4*h + g

// ---------------- GEMM tiling ----------------
#define BM 128
#define BN 128
#define THREADS 512
#define NSTAGES 3
#define KITERS2 32                   // mainloop iterations, 64 K each
#define SUB_A_U4 512                 // one 32-K A subtile (128 rows) in uint4
#define SUB_B_U4 512
#define A_TILE_U4 (2 * SUB_A_U4)     // 64-K stage A = 1024 uint4 = 16KB
#define B_TILE_U4 (2 * SUB_B_U4)     // 16KB
#define A_BYTES (A_TILE_U4 * 16)     // 16384
#define B_BYTES (B_TILE_U4 * 16)     // 16384
#define STAGE_BYTES (A_BYTES + B_BYTES)        // 32768
#define STAGE_REGION (NSTAGES * STAGE_BYTES)   // 98304
#define EPI_STRIDE 132
#define EPI_BYTES (BM * EPI_STRIDE * 4)        // 67584 (overlays stage region)
#define OFF_BIAS STAGE_REGION
#define SMEM_TOTAL (STAGE_REGION + 512)        // 98816  -> 2 CTAs/SM

// ---------------- scratch: fragment-ordered fp16 operands ----------------
// g_A: [mb(64 x 128-row)][kt32(64)][m16(8)][ks(2)][lane(32)] x uint4
//      uint4 = {h2(A[R][C..]), h2(A[R+8][C..]), h2(A[R][C+8..]), h2(A[R+8][C+8..])}
__device__ uint4 g_A[(size_t)BB * KTOT / 8];
// g_B: [nb(32)][kt32(64)][wn(4)][p(2)][ks(2)][lane(32)] x uint4
__device__ uint4 g_B[(size_t)NNI * KTOT / 8];
__device__ float g_bias[NNI];   // interleaved 4h+g

// ---------------- helpers ----------------
__device__ __forceinline__ void cpa16(uint32_t s, const void* g) {
    asm volatile("cp.async.cg.shared.global [%0], [%1], 16;" :: "r"(s), "l"(g));
}

__device__ __forceinline__ uint32_t h2pack(float lo, float hi) {
    __half2 h = __floats2half2_rn(lo, hi);
    return *reinterpret_cast<uint32_t*>(&h);
}

__device__ __forceinline__ void mma_f16(float* d, const uint4& a, uint32_t b0, uint32_t b1) {
    asm volatile(
        "mma.sync.aligned.m16n8k16.row.col.f32.f16.f16.f32 "
        "{%0,%1,%2,%3}, {%4,%5,%6,%7}, {%8,%9}, {%0,%1,%2,%3};"
        : "+f"(d[0]), "+f"(d[1]), "+f"(d[2]), "+f"(d[3])
        : "r"(a.x), "r"(a.y), "r"(a.z), "r"(a.w), "r"(b0), "r"(b1));
}

__device__ __forceinline__ float fast_sigmoid(float x) {
    return __fdividef(1.0f, 1.0f + __expf(-x));
}
__device__ __forceinline__ float fast_tanh(float x) {
    return __fmaf_rn(2.0f, __fdividef(1.0f, 1.0f + __expf(-2.0f * x)), -1.0f);
}

// ================= pre-pass: fp16-round + concat + fragment-order =================
__global__ __launch_bounds__(256) void convert_A(const float* __restrict__ X,
                                                 const float* __restrict__ Hs) {
    size_t idx = (size_t)blockIdx.x * 256 + threadIdx.x;   // uint4 entries, 2^21 total
    int lane = (int)(idx & 31);
    int ks   = (int)((idx >> 5) & 1);
    int m16  = (int)((idx >> 6) & 7);
    int kt   = (int)((idx >> 9) & 63);
    int mb   = (int)(idx >> 15);
    int qr = lane >> 2, qc = lane & 3;
    int R = mb * 128 + m16 * 16 + qr;
    int C = kt * 32 + ks * 16 + 2 * qc;

    const float* src = (C < 1024) ? X : Hs;
    int c0 = C & 1023;
    float2 r0a = *(const float2*)&src[(size_t)R * 1024 + c0];
    float2 r0b = *(const float2*)&src[(size_t)R * 1024 + c0 + 8];
    float2 r1a = *(const float2*)&src[(size_t)(R + 8) * 1024 + c0];
    float2 r1b = *(const float2*)&src[(size_t)(R + 8) * 1024 + c0 + 8];

    uint4 o;
    o.x = h2pack(r0a.x, r0a.y);
    o.y = h2pack(r1a.x, r1a.y);
    o.z = h2pack(r0b.x, r0b.y);
    o.w = h2pack(r1b.x, r1b.y);
    g_A[idx] = o;
}

__global__ __launch_bounds__(256) void convert_B(const float* __restrict__ Wx,
                                                 const float* __restrict__ Wh,
                                                 const float* __restrict__ bx,
                                                 const float* __restrict__ bh) {
    size_t idx = (size_t)blockIdx.x * 256 + threadIdx.x;   // uint4 entries, 2^20 total
    int lane = (int)(idx & 31);
    int ks   = (int)((idx >> 5) & 1);
    int p    = (int)((idx >> 6) & 1);
    int wn   = (int)((idx >> 7) & 3);
    int kt   = (int)((idx >> 9) & 63);
    int nb   = (int)(idx >> 15);
    int qr = lane >> 2, qc = lane & 3;
    int C = kt * 32 + ks * 16 + 2 * qc;
    int N0 = nb * 128 + wn * 32 + p * 16 + qr;
    int N1 = N0 + 8;
    int sr0 = (N0 & 3) * 1024 + (N0 >> 2);    // n' = 4h+g -> row g*1024+h
    int sr1 = (N1 & 3) * 1024 + (N1 >> 2);

    const float* src = (C < 1024) ? Wx : Wh;
    int c0 = C & 1023;
    float2 w0a = *(const float2*)&src[(size_t)sr0 * 1024 + c0];
    float2 w0b = *(const float2*)&src[(size_t)sr0 * 1024 + c0 + 8];
    float2 w1a = *(const float2*)&src[(size_t)sr1 * 1024 + c0];
    float2 w1b = *(const float2*)&src[(size_t)sr1 * 1024 + c0 + 8];

    uint4 o;
    o.x = h2pack(w0a.x, w0a.y);
    o.y = h2pack(w0b.x, w0b.y);
    o.z = h2pack(w1a.x, w1a.y);
    o.w = h2pack(w1b.x, w1b.y);
    g_B[idx] = o;

    if (kt == 0 && ks == 0 && qc == 0) {
        g_bias[N0] = bx[sr0] + bh[sr0];
        g_bias[N1] = bx[sr1] + bh[sr1];
    }
}

// ================= fused GEMM + LSTM epilogue (2 CTAs/SM) =================
__global__ __launch_bounds__(THREADS, 2) void lstm_gemm(const float* __restrict__ cin,
                                                        float* __restrict__ out) {
    extern __shared__ char smem[];
    float* smf = (float*)smem;
    const int tid  = threadIdx.x;
    const int lane = tid & 31;
    const int wid  = tid >> 5;
    const int wm   = wid >> 2;      // 4 warps over M (32 rows each)
    const int wn   = wid & 3;       // 4 warps over N (32 cols each)
    const int qr   = lane >> 2;
    const int qc   = lane & 3;

    const int mb = blockIdx.y;      // 0..63
    const int nb = blockIdx.x;      // 0..31
    const int m_base = mb * BM;
    const int hb = nb * 32;

    uint32_t sb;
    asm("{ .reg .u64 t; cvta.to.shared.u64 t, %1; cvt.u32.u64 %0, t; }" : "=r"(sb) : "l"(smem));

    if (tid < 128) smf[OFF_BIAS / 4 + tid] = g_bias[nb * 128 + tid];

    float acc[2][4][4] = {};

    const uint4* gA4 = g_A + ((size_t)mb * 64) * SUB_A_U4;
    const uint4* gB4 = g_B + ((size_t)nb * 64) * SUB_B_U4;

    // ---- prologue: fill stages 0..1 ----
#pragma unroll
    for (int s = 0; s < NSTAGES - 1; s++) {
        uint32_t base = sb + (uint32_t)s * STAGE_BYTES;
        const uint4* a_src = gA4 + (size_t)s * A_TILE_U4;
        const uint4* b_src = gB4 + (size_t)s * B_TILE_U4;
#pragma unroll
        for (int j = 0; j < 2; j++) {
            int ch = j * THREADS + tid;
            cpa16(base + (uint32_t)ch * 16u, a_src + ch);
        }
#pragma unroll
        for (int j = 0; j < 2; j++) {
            int ch = j * THREADS + tid;
            cpa16(base + (uint32_t)(A_BYTES + ch * 16), b_src + ch);
        }
        asm volatile("cp.async.commit_group;");
    }

#pragma unroll 1
    for (int it = 0; it < KITERS2; ++it) {
        asm volatile("cp.async.wait_group %0;" :: "n"(NSTAGES - 2));
        __syncthreads();

        if (it + NSTAGES - 1 < KITERS2) {
            const int ns = (it + NSTAGES - 1) % NSTAGES;
            uint32_t base = sb + (uint32_t)ns * STAGE_BYTES;
            const uint4* a_src = gA4 + (size_t)(it + NSTAGES - 1) * A_TILE_U4;
            const uint4* b_src = gB4 + (size_t)(it + NSTAGES - 1) * B_TILE_U4;
#pragma unroll
            for (int j = 0; j < 2; j++) {
                int ch = j * THREADS + tid;
                cpa16(base + (uint32_t)ch * 16u, a_src + ch);
            }
#pragma unroll
            for (int j = 0; j < 2; j++) {
                int ch = j * THREADS + tid;
                cpa16(base + (uint32_t)(A_BYTES + ch * 16), b_src + ch);
            }
        }
        asm volatile("cp.async.commit_group;");   // empty commit in tail keeps count

        const int cur = it % NSTAGES;
        const uint4* sA = (const uint4*)(smem + cur * STAGE_BYTES) + lane;
        const uint4* sB = (const uint4*)(smem + cur * STAGE_BYTES + A_BYTES) + lane;

#pragma unroll
        for (int ks2 = 0; ks2 < 4; ks2++) {       // 4 x 16-K steps per iteration
            const int aoff = (ks2 >> 1) * SUB_A_U4 + (ks2 & 1) * 32;
            const int boff = (ks2 >> 1) * SUB_B_U4 + (ks2 & 1) * 32;
            uint4 a0 = sA[aoff + (wm * 2 + 0) * 64];
            uint4 a1 = sA[aoff + (wm * 2 + 1) * 64];
            uint4 b0 = sB[boff + (wn * 2 + 0) * 64];
            uint4 b1 = sB[boff + (wn * 2 + 1) * 64];
#pragma unroll
            for (int mf = 0; mf < 2; mf++) {
                const uint4& a = (mf == 0) ? a0 : a1;
                mma_f16(acc[mf][0], a, b0.x, b0.y);
                mma_f16(acc[mf][1], a, b0.z, b0.w);
                mma_f16(acc[mf][2], a, b1.x, b1.y);
                mma_f16(acc[mf][3], a, b1.z, b1.w);
            }
        }
    }

    // ---------------- fused epilogue ----------------
    asm volatile("cp.async.wait_group 0;");
    __syncthreads();   // all compute + async writes done before overlaying stage region
    {
        const int col0 = wn * 32;
#pragma unroll
        for (int mf = 0; mf < 2; mf++) {
            int r = wm * 32 + mf * 16 + qr;
#pragma unroll
            for (int nf = 0; nf < 4; nf++) {
                int cL = col0 + nf * 8 + 2 * qc;
                *(float2*)&smf[r * EPI_STRIDE + cL] = make_float2(acc[mf][nf][0], acc[mf][nf][1]);
                *(float2*)&smf[(r + 8) * EPI_STRIDE + cL] = make_float2(acc[mf][nf][2], acc[mf][nf][3]);
            }
        }
    }
    __syncthreads();

    {
        const int hl = tid & 31;          // h within block
        const int rg = tid >> 5;          // 0..15
        float4 bv = *(float4*)&smf[OFF_BIAS / 4 + hl * 4];
        const int h = hb + hl;
#pragma unroll 1
        for (int i = 0; i < 8; i++) {
            int r = i * 16 + rg;
            float4 gt = *(float4*)&smf[r * EPI_STRIDE + hl * 4];
            size_t oidx = (size_t)(m_base + r) * HH + h;
            float cc = cin[oidx];
            float ig = fast_sigmoid(gt.x + bv.x);
            float fg = fast_sigmoid(gt.y + bv.y);
            float g2 = fast_tanh(gt.z + bv.z);
            float og = fast_sigmoid(gt.w + bv.w);
            float nc = fg * cc + ig * g2;
            float nh = og * fast_tanh(nc);
            out[oidx] = nh;
            out[oidx + (size_t)BB * HH] = nh;
            out[oidx + 2 * (size_t)BB * HH] = nc;
        }
    }
}

// ================= launch =================
extern "C" void kernel_launch(void* const* d_in, const int* in_sizes, int n_in,
                              void* d_out, int out_size) {
    const float* X  = (const float*)d_in[0];
    const float* Hs = (const float*)d_in[1];
    const float* c  = (const float*)d_in[2];
    const float* Wx = (const float*)d_in[3];
    const float* Wh = (const float*)d_in[4];
    const float* bx = (const float*)d_in[5];
    const float* bh = (const float*)d_in[6];
    float* out = (float*)d_out;

    cudaFuncSetAttribute(lstm_gemm, cudaFuncAttributeMaxDynamicSharedMemorySize, SMEM_TOTAL);

    convert_A<<<(BB * KTOT / 8) / 256, 256>>>(X, Hs);
    convert_B<<<(NNI * KTOT / 8) / 256, 256>>>(Wx, Wh, bx, bh);
    lstm_gemm<<<dim3(NNI / BN, BB / BM), THREADS, SMEM_TOTAL>>>(c, out);
}